// round 4
// baseline (speedup 1.0000x reference)
#include <cuda_runtime.h>

// context[b,d] = sum_t keys[b,t,d]   (softmax over size-1 axis == 1; rest dead)
// R4: single launch. Contiguous-streaming slab blocks write partials; the
// LAST block of each batch (per-batch atomic counter) reduces the 19 partials
// and writes the output. Float accumulation order is fixed -> deterministic.

#define B_SZ   32
#define D4     128          // 512 floats = 128 float4 per row
#define NSLAB  19           // 32*19 = 608 blocks = 2 * (152 SMs * 2 blocks)
#define NGRP   512          // 4096 rows / 8 rows-per-iteration
#define GPS    27           // groups per slab (last slab gets 512-18*27 = 26)

__device__ float4 g_partial[B_SZ * NSLAB * D4];   // 1.2 MB scratch
__device__ int    g_cnt[B_SZ];                    // zero-init; reset by finalizer

__global__ __launch_bounds__(1024, 2)
void keys_sum_fused_kernel(const float4* __restrict__ keys4,
                           float4* __restrict__ out4) {
    const int bid = blockIdx.x;            // 0..607
    const int b   = bid / NSLAB;
    const int s   = bid - b * NSLAB;
    const int g0  = s * GPS;
    const int ng  = (s == NSLAB - 1) ? (NGRP - g0) : GPS;   // 27 or 26
    const int tid = threadIdx.x;

    // ---- phase 1: stream 16 KB/iter fully contiguous, column = tid & 127 ----
    const float4* p = keys4 + b * (4096 * D4) + g0 * 1024 + tid;

    float4 acc = make_float4(0.f, 0.f, 0.f, 0.f);
    #pragma unroll 4
    for (int i = 0; i < ng; ++i) {
        float4 v = __ldcs(p + i * 1024);
        acc.x += v.x; acc.y += v.y; acc.z += v.z; acc.w += v.w;
    }

    __shared__ float4 sm[1024];
    sm[tid] = acc;
    __syncthreads();
    if (tid < 512) {
        float4 o = sm[tid + 512];
        sm[tid].x += o.x; sm[tid].y += o.y; sm[tid].z += o.z; sm[tid].w += o.w;
    }
    __syncthreads();
    if (tid < 256) {
        float4 o = sm[tid + 256];
        sm[tid].x += o.x; sm[tid].y += o.y; sm[tid].z += o.z; sm[tid].w += o.w;
    }
    __syncthreads();
    if (tid < 128) {
        float4 m = sm[tid];
        float4 o = sm[tid + 128];
        m.x += o.x; m.y += o.y; m.z += o.z; m.w += o.w;
        g_partial[(b * NSLAB + s) * D4 + tid] = m;
    }

    // ---- phase 2: last block of this batch reduces the 19 partials ----
    __threadfence();                       // partials visible chip-wide
    __syncthreads();

    __shared__ int is_last;
    if (tid == 0)
        is_last = (atomicAdd(&g_cnt[b], 1) == NSLAB - 1);
    __syncthreads();
    if (!is_last) return;
    __threadfence();                       // acquire partials of other blocks

    // 1024 threads = 128 columns x 8 slab-groups; slabs s = grp, grp+8, grp+16
    const int col = tid & 127;
    const int grp = tid >> 7;              // 0..7
    float4 a = make_float4(0.f, 0.f, 0.f, 0.f);
    #pragma unroll
    for (int ss = grp; ss < NSLAB; ss += 8) {
        float4 v = g_partial[(b * NSLAB + ss) * D4 + col];
        a.x += v.x; a.y += v.y; a.z += v.z; a.w += v.w;
    }
    sm[tid] = a;
    __syncthreads();
    if (tid < 512) {
        float4 o = sm[tid + 512];
        sm[tid].x += o.x; sm[tid].y += o.y; sm[tid].z += o.z; sm[tid].w += o.w;
    }
    __syncthreads();
    if (tid < 256) {
        float4 o = sm[tid + 256];
        sm[tid].x += o.x; sm[tid].y += o.y; sm[tid].z += o.z; sm[tid].w += o.w;
    }
    __syncthreads();
    if (tid < 128) {
        float4 m = sm[tid];
        float4 o = sm[tid + 128];
        m.x += o.x; m.y += o.y; m.z += o.z; m.w += o.w;
        out4[b * D4 + tid] = m;
    }
    if (tid == 0) g_cnt[b] = 0;            // reset for next graph replay
}

extern "C" void kernel_launch(void* const* d_in, const int* in_sizes, int n_in,
                              void* d_out, int out_size) {
    // metadata order: query[0], keys[1], Ws[2], Wh[3], W[4]; only keys is live.
    const float4* keys4 = (const float4*)d_in[1];
    float4* out4 = (float4*)d_out;

    keys_sum_fused_kernel<<<B_SZ * NSLAB, 1024>>>(keys4, out4);
}

// round 5
// speedup vs baseline: 1.1129x; 1.1129x over previous
#include <cuda_runtime.h>

// context[b,d] = sum_t keys[b,t,d]   (softmax over size-1 axis == 1; rest dead)
// R5: back to the R2 single-kernel design (no partials/fences/atomics), with
// a better-balanced grid: 512 blocks x 512 threads -> 3-4 blocks/SM resident
// for the whole kernel (R2's 256-block grid left 48 SMs half-loaded).

#define B_SZ   32
#define T_LEN  4096
#define D4     128           // 512 floats = 128 float4 per row
#define NCHUNK 16            // 16 chunks of 8 float4 columns
#define CW     8             // columns per chunk (float4)

// Block = (chunk, b). 512 threads = 8 float4-columns x 64 T-partitions.
// Each thread streams 64 rows of one float4 column; smem reduce partitions.
__global__ __launch_bounds__(512, 4)
void keys_sum_kernel(const float4* __restrict__ keys4, float4* __restrict__ out4) {
    const int tid   = threadIdx.x;
    const int col   = tid & (CW - 1);     // 0..7 within chunk
    const int part  = tid >> 3;           // 0..63 T-partition
    const int chunk = blockIdx.x;         // 0..15
    const int b     = blockIdx.y;         // 0..31

    const int col4 = chunk * CW + col;    // global float4 column 0..127
    // 32-bit index is safe: max 32*4096*128 = 16.7M float4
    int idx = (b * T_LEN + part * 64) * D4 + col4;

    float4 acc = make_float4(0.f, 0.f, 0.f, 0.f);
    #pragma unroll 8
    for (int i = 0; i < 64; ++i) {
        float4 v = __ldcs(&keys4[idx]);   // streaming, zero reuse
        idx += D4;
        acc.x += v.x; acc.y += v.y; acc.z += v.z; acc.w += v.w;
    }

    __shared__ float4 sm[512];
    sm[tid] = acc;
    __syncthreads();

    // reduce across the 64 T-partitions (stride-8 layout keeps per-col sums)
    #pragma unroll
    for (int s = 256; s >= 8; s >>= 1) {
        if (tid < s) {
            float4 o = sm[tid + s];
            float4 m = sm[tid];
            m.x += o.x; m.y += o.y; m.z += o.z; m.w += o.w;
            sm[tid] = m;
        }
        __syncthreads();
    }

    if (tid < CW) {
        out4[b * D4 + chunk * CW + tid] = sm[tid];
    }
}

extern "C" void kernel_launch(void* const* d_in, const int* in_sizes, int n_in,
                              void* d_out, int out_size) {
    // metadata order: query[0], keys[1], Ws[2], Wh[3], W[4]; only keys is live.
    const float* keys = (const float*)d_in[1];
    float* out = (float*)d_out;

    dim3 grid(NCHUNK, B_SZ);   // (16, 32) = 512 blocks
    keys_sum_kernel<<<grid, 512>>>((const float4*)keys, (float4*)out);
}